// round 1
// baseline (speedup 1.0000x reference)
#include <cuda_runtime.h>
#include <math.h>

// ---------------- problem constants ----------------
#define Bb 4
#define Ss 512
#define Dd 1024
#define Hh 16
#define DKk 64
#define DFFf 4096
#define Ll 6
#define Mm (Bb*Ss)      // 2048
#define BHh (Bb*Hh)     // 64

// ---------------- scratch (static device memory; no allocation) ----------------
__device__ float g_x[Mm*Dd];
__device__ float g_q[Mm*Dd];
__device__ float g_k[Mm*Dd];
__device__ float g_v[Mm*Dd];
__device__ float g_ctx[Mm*Dd];
__device__ float g_proj[Mm*Dd];
__device__ float g_scores[BHh*Ss*Ss];
__device__ float g_ffn[Mm*DFFf];

// ---------------- embedding ----------------
__global__ void embed_kernel(const int* __restrict__ ids,
                             const float* __restrict__ tok,
                             const float* __restrict__ pos)
{
    int idx = blockIdx.x * blockDim.x + threadIdx.x;   // over Mm*Dd
    int row = idx >> 10;          // / Dd
    int d   = idx & (Dd - 1);
    int s   = row & (Ss - 1);
    g_x[idx] = tok[(size_t)ids[row] * Dd + d] + pos[(size_t)s * Dd + d];
}

// ---------------- classic 128x128x8 fp32 SGEMM, C = A[M,K] @ B[K,N] ----------------
__global__ __launch_bounds__(256) void sgemm_kernel(
    const float* __restrict__ A, const float* __restrict__ Bm,
    float* __restrict__ C, int N, int K, int relu)
{
    __shared__ float As[8][128];
    __shared__ float Bs[8][128];
    const int tid = threadIdx.x;
    const int tx = tid & 15, ty = tid >> 4;
    const int a_row = tid >> 1;           // 0..127
    const int a_col = (tid & 1) * 4;      // 0 or 4
    const int b_row = tid >> 5;           // 0..7
    const int b_col = (tid & 31) * 4;     // 0..124
    const float* Ab = A + (size_t)blockIdx.y * 128 * K;
    const float* Bbp = Bm + blockIdx.x * 128;
    float acc[8][8];
    #pragma unroll
    for (int i = 0; i < 8; i++)
        #pragma unroll
        for (int j = 0; j < 8; j++) acc[i][j] = 0.f;

    for (int k0 = 0; k0 < K; k0 += 8) {
        float4 av = *(const float4*)(Ab + (size_t)a_row * K + k0 + a_col);
        As[a_col + 0][a_row] = av.x;
        As[a_col + 1][a_row] = av.y;
        As[a_col + 2][a_row] = av.z;
        As[a_col + 3][a_row] = av.w;
        float4 bv = *(const float4*)(Bbp + (size_t)(k0 + b_row) * N + b_col);
        *(float4*)&Bs[b_row][b_col] = bv;
        __syncthreads();
        #pragma unroll
        for (int kk = 0; kk < 8; kk++) {
            float4 a0 = *(const float4*)&As[kk][ty * 8];
            float4 a1 = *(const float4*)&As[kk][ty * 8 + 4];
            float4 b0 = *(const float4*)&Bs[kk][tx * 8];
            float4 b1 = *(const float4*)&Bs[kk][tx * 8 + 4];
            float ar[8] = {a0.x, a0.y, a0.z, a0.w, a1.x, a1.y, a1.z, a1.w};
            float br[8] = {b0.x, b0.y, b0.z, b0.w, b1.x, b1.y, b1.z, b1.w};
            #pragma unroll
            for (int i = 0; i < 8; i++)
                #pragma unroll
                for (int j = 0; j < 8; j++)
                    acc[i][j] = fmaf(ar[i], br[j], acc[i][j]);
        }
        __syncthreads();
    }
    float* Cb = C + ((size_t)blockIdx.y * 128 + ty * 8) * N + blockIdx.x * 128 + tx * 8;
    #pragma unroll
    for (int i = 0; i < 8; i++) {
        #pragma unroll
        for (int j = 0; j < 8; j += 4) {
            float4 o;
            o.x = acc[i][j]; o.y = acc[i][j+1]; o.z = acc[i][j+2]; o.w = acc[i][j+3];
            if (relu) {
                o.x = fmaxf(o.x, 0.f); o.y = fmaxf(o.y, 0.f);
                o.z = fmaxf(o.z, 0.f); o.w = fmaxf(o.w, 0.f);
            }
            *(float4*)(Cb + (size_t)i * N + j) = o;
        }
    }
}

// ---------------- scores: S_bh[q,k] = (Q_bh . K_bh) / 8 ----------------
// grid: (8 ktiles, 8 qtiles, B*H). 64x64 tile per block, 256 threads, 4x4/thread.
__global__ __launch_bounds__(256) void scores_kernel()
{
    __shared__ float Qs[64][65];
    __shared__ float Ks[64][65];
    int bh = blockIdx.z, b = bh >> 4, h = bh & 15;
    int q0 = blockIdx.y * 64, k0 = blockIdx.x * 64;
    int tid = threadIdx.x;
    int lr = tid >> 4, lc = (tid & 15) << 2;
    const float* Qb = g_q + ((size_t)b * Ss + q0) * Dd + h * DKk;
    const float* Kb = g_k + ((size_t)b * Ss + k0) * Dd + h * DKk;
    #pragma unroll
    for (int it = 0; it < 4; it++) {
        int r = lr + it * 16;
        float4 qv = *(const float4*)(Qb + (size_t)r * Dd + lc);
        Qs[r][lc] = qv.x; Qs[r][lc+1] = qv.y; Qs[r][lc+2] = qv.z; Qs[r][lc+3] = qv.w;
        float4 kv = *(const float4*)(Kb + (size_t)r * Dd + lc);
        Ks[r][lc] = kv.x; Ks[r][lc+1] = kv.y; Ks[r][lc+2] = kv.z; Ks[r][lc+3] = kv.w;
    }
    __syncthreads();
    int ty = tid >> 4, tx = tid & 15;
    float acc[4][4] = {};
    #pragma unroll
    for (int kk = 0; kk < 64; kk++) {
        float ar[4], br[4];
        #pragma unroll
        for (int i = 0; i < 4; i++) ar[i] = Qs[ty * 4 + i][kk];
        #pragma unroll
        for (int j = 0; j < 4; j++) br[j] = Ks[tx * 4 + j][kk];
        #pragma unroll
        for (int i = 0; i < 4; i++)
            #pragma unroll
            for (int j = 0; j < 4; j++)
                acc[i][j] = fmaf(ar[i], br[j], acc[i][j]);
    }
    float* out = g_scores + ((size_t)bh * Ss + q0 + ty * 4) * Ss + k0 + tx * 4;
    #pragma unroll
    for (int i = 0; i < 4; i++)
        #pragma unroll
        for (int j = 0; j < 4; j++)
            out[(size_t)i * Ss + j] = acc[i][j] * 0.125f;
}

// ---------------- fused mask + softmax over k (row length 512) ----------------
__global__ __launch_bounds__(256) void softmax_kernel(
    const float* __restrict__ src, float* __restrict__ dst,
    const int* __restrict__ ids, int masked)
{
    __shared__ float sh[8];
    int bhq = blockIdx.x;
    int q = bhq & (Ss - 1);
    int b = bhq >> 13;                       // / (H*S) = /8192
    const float* row = src + (size_t)bhq * Ss;
    float* orow = dst + (size_t)bhq * Ss;
    int tid = threadIdx.x;

    int k0 = tid, k1 = tid + 256;
    float v0 = row[k0], v1 = row[k1];
    if (masked) {
        if (k0 > q || ids[b * Ss + k0] == 0) v0 = -1e9f;
        if (k1 > q || ids[b * Ss + k1] == 0) v1 = -1e9f;
    }
    float m = fmaxf(v0, v1);
    #pragma unroll
    for (int o = 16; o; o >>= 1) m = fmaxf(m, __shfl_xor_sync(0xffffffffu, m, o));
    if ((tid & 31) == 0) sh[tid >> 5] = m;
    __syncthreads();
    m = sh[0];
    #pragma unroll
    for (int w = 1; w < 8; w++) m = fmaxf(m, sh[w]);

    float e0 = expf(v0 - m), e1 = expf(v1 - m);
    float s = e0 + e1;
    #pragma unroll
    for (int o = 16; o; o >>= 1) s += __shfl_xor_sync(0xffffffffu, s, o);
    __syncthreads();
    if ((tid & 31) == 0) sh[tid >> 5] = s;
    __syncthreads();
    s = 0.f;
    #pragma unroll
    for (int w = 0; w < 8; w++) s += sh[w];
    float inv = 1.0f / s;
    orow[k0] = e0 * inv;
    orow[k1] = e1 * inv;
}

// ---------------- ctx: C_bh[q,d] = P_bh[q,:] @ V_bh[:,d] ----------------
// grid: (8 qtiles, 1, B*H). 64x64 per block, 256 threads, 4x4/thread.
__global__ __launch_bounds__(256) void ctx_kernel(const float* __restrict__ P)
{
    __shared__ float Ps[64][33];
    __shared__ float Vs[32][65];
    int bh = blockIdx.z, b = bh >> 4, h = bh & 15;
    int q0 = blockIdx.x * 64;
    int tid = threadIdx.x;
    const float* Pb = P + ((size_t)bh * Ss + q0) * Ss;
    const float* Vb = g_v + (size_t)b * Ss * Dd + h * DKk;
    int pr = tid >> 3, pc = (tid & 7) << 2;    // 32 rows/pass x 32 cols
    int vr = tid >> 4, vc = (tid & 15) << 2;   // 16 rows/pass x 64 cols
    int ty = tid >> 4, tx = tid & 15;
    float acc[4][4] = {};
    for (int kb = 0; kb < Ss; kb += 32) {
        #pragma unroll
        for (int it = 0; it < 2; it++) {
            int r = pr + it * 32;
            float4 pv = *(const float4*)(Pb + (size_t)r * Ss + kb + pc);
            Ps[r][pc] = pv.x; Ps[r][pc+1] = pv.y; Ps[r][pc+2] = pv.z; Ps[r][pc+3] = pv.w;
            int r2 = vr + it * 16;
            float4 vv = *(const float4*)(Vb + (size_t)(kb + r2) * Dd + vc);
            Vs[r2][vc] = vv.x; Vs[r2][vc+1] = vv.y; Vs[r2][vc+2] = vv.z; Vs[r2][vc+3] = vv.w;
        }
        __syncthreads();
        #pragma unroll
        for (int kk = 0; kk < 32; kk++) {
            float ar[4], br[4];
            #pragma unroll
            for (int i = 0; i < 4; i++) ar[i] = Ps[ty * 4 + i][kk];
            #pragma unroll
            for (int j = 0; j < 4; j++) br[j] = Vs[kk][tx * 4 + j];
            #pragma unroll
            for (int i = 0; i < 4; i++)
                #pragma unroll
                for (int j = 0; j < 4; j++)
                    acc[i][j] = fmaf(ar[i], br[j], acc[i][j]);
        }
        __syncthreads();
    }
    float* out = g_ctx + ((size_t)b * Ss + q0 + ty * 4) * Dd + h * DKk + tx * 4;
    #pragma unroll
    for (int i = 0; i < 4; i++)
        #pragma unroll
        for (int j = 0; j < 4; j++)
            out[(size_t)i * Dd + j] = acc[i][j];
}

// ---------------- fused residual + LayerNorm (row = 1024) ----------------
__global__ __launch_bounds__(256) void ln_kernel(
    const float* __restrict__ hb, const float* __restrict__ res,
    const float* __restrict__ g, const float* __restrict__ bta,
    float* __restrict__ out)
{
    __shared__ float sh[8];
    int row = blockIdx.x, tid = threadIdx.x;
    const float* hr = hb + (size_t)row * Dd;
    const float* rr = res + (size_t)row * Dd;
    float v[4];
    #pragma unroll
    for (int i = 0; i < 4; i++) v[i] = hr[tid + i * 256] + rr[tid + i * 256];

    float s = v[0] + v[1] + v[2] + v[3];
    #pragma unroll
    for (int o = 16; o; o >>= 1) s += __shfl_xor_sync(0xffffffffu, s, o);
    if ((tid & 31) == 0) sh[tid >> 5] = s;
    __syncthreads();
    s = 0.f;
    #pragma unroll
    for (int w = 0; w < 8; w++) s += sh[w];
    float mean = s * (1.0f / Dd);

    float qs = 0.f;
    #pragma unroll
    for (int i = 0; i < 4; i++) { float d0 = v[i] - mean; qs = fmaf(d0, d0, qs); }
    #pragma unroll
    for (int o = 16; o; o >>= 1) qs += __shfl_xor_sync(0xffffffffu, qs, o);
    __syncthreads();
    if ((tid & 31) == 0) sh[tid >> 5] = qs;
    __syncthreads();
    qs = 0.f;
    #pragma unroll
    for (int w = 0; w < 8; w++) qs += sh[w];
    float var = qs * (1.0f / Dd);
    float scale = rsqrtf(var + 1e-5f);

    #pragma unroll
    for (int i = 0; i < 4; i++) {
        int c = tid + i * 256;
        out[(size_t)row * Dd + c] = (v[i] - mean) * scale * g[c] + bta[c];
    }
}

__global__ void copy_kernel(const float* __restrict__ src, float* __restrict__ dst)
{
    int i = blockIdx.x * blockDim.x + threadIdx.x;   // over Mm*Dd/4 float4s
    ((float4*)dst)[i] = ((const float4*)src)[i];
}

// ---------------- host orchestration ----------------
extern "C" void kernel_launch(void* const* d_in, const int* in_sizes, int n_in,
                              void* d_out, int out_size)
{
    (void)in_sizes; (void)n_in; (void)out_size;
    const int*   ids  = (const int*)  d_in[0];
    const float* tok  = (const float*)d_in[1];
    const float* pos  = (const float*)d_in[2];
    const float* Wq1  = (const float*)d_in[3];
    const float* Wk1  = (const float*)d_in[4];
    const float* Wv1  = (const float*)d_in[5];
    const float* Wo1  = (const float*)d_in[6];
    const float* g1   = (const float*)d_in[7];
    const float* b1   = (const float*)d_in[8];
    const float* Wq2  = (const float*)d_in[9];
    const float* Wk2  = (const float*)d_in[10];
    const float* Wv2  = (const float*)d_in[11];
    const float* Wo2  = (const float*)d_in[12];
    const float* g2   = (const float*)d_in[13];
    const float* b2   = (const float*)d_in[14];
    const float* Wff1 = (const float*)d_in[15];
    const float* Wff2 = (const float*)d_in[16];
    const float* gff  = (const float*)d_in[17];
    const float* bff  = (const float*)d_in[18];

    float* out = (float*)d_out;
    float* x_out = out;
    float* attn_out = out + (size_t)Mm * Dd;

    float *px, *pq, *pk, *pv, *pctx, *pproj, *pscores, *pffn;
    cudaGetSymbolAddress((void**)&px,     g_x);
    cudaGetSymbolAddress((void**)&pq,     g_q);
    cudaGetSymbolAddress((void**)&pk,     g_k);
    cudaGetSymbolAddress((void**)&pv,     g_v);
    cudaGetSymbolAddress((void**)&pctx,   g_ctx);
    cudaGetSymbolAddress((void**)&pproj,  g_proj);
    cudaGetSymbolAddress((void**)&pscores,g_scores);
    cudaGetSymbolAddress((void**)&pffn,   g_ffn);

    embed_kernel<<<(Mm * Dd) / 256, 256>>>(ids, tok, pos);

    const dim3 gProj(Dd / 128, Mm / 128);     // 8 x 16
    const dim3 gFfn1(DFFf / 128, Mm / 128);   // 32 x 16
    const dim3 gScores(8, 8, BHh);
    const dim3 gCtx(8, 1, BHh);

    for (int i = 0; i < Ll; i++) {
        // ---- MHA1 (masked self-attn, attn not output) ----
        sgemm_kernel<<<gProj, 256>>>(px, Wq1 + (size_t)i * Dd * Dd, pq, Dd, Dd, 0);
        sgemm_kernel<<<gProj, 256>>>(px, Wk1 + (size_t)i * Dd * Dd, pk, Dd, Dd, 0);
        sgemm_kernel<<<gProj, 256>>>(px, Wv1 + (size_t)i * Dd * Dd, pv, Dd, Dd, 0);
        scores_kernel<<<gScores, 256>>>();
        softmax_kernel<<<BHh * Ss, 256>>>(pscores, pscores, ids, 1);
        ctx_kernel<<<gCtx, 256>>>(pscores);
        sgemm_kernel<<<gProj, 256>>>(pctx, Wo1 + (size_t)i * Dd * Dd, pproj, Dd, Dd, 0);
        ln_kernel<<<Mm, 256>>>(pproj, px, g1 + (size_t)i * Dd, b1 + (size_t)i * Dd, px);

        // ---- MHA2 (no mask; attn written to output) ----
        float* attn_i = attn_out + (size_t)i * BHh * Ss * Ss;
        sgemm_kernel<<<gProj, 256>>>(px, Wq2 + (size_t)i * Dd * Dd, pq, Dd, Dd, 0);
        sgemm_kernel<<<gProj, 256>>>(px, Wk2 + (size_t)i * Dd * Dd, pk, Dd, Dd, 0);
        sgemm_kernel<<<gProj, 256>>>(px, Wv2 + (size_t)i * Dd * Dd, pv, Dd, Dd, 0);
        scores_kernel<<<gScores, 256>>>();
        softmax_kernel<<<BHh * Ss, 256>>>(pscores, attn_i, ids, 0);
        ctx_kernel<<<gCtx, 256>>>(attn_i);
        sgemm_kernel<<<gProj, 256>>>(pctx, Wo2 + (size_t)i * Dd * Dd, pproj, Dd, Dd, 0);
        ln_kernel<<<Mm, 256>>>(pproj, px, g2 + (size_t)i * Dd, b2 + (size_t)i * Dd, px);

        // ---- FFN ----
        sgemm_kernel<<<gFfn1, 256>>>(px, Wff1 + (size_t)i * Dd * DFFf, pffn, DFFf, Dd, 1);
        sgemm_kernel<<<gProj, 256>>>(pffn, Wff2 + (size_t)i * DFFf * Dd, pproj, Dd, DFFf, 0);
        ln_kernel<<<Mm, 256>>>(pproj, px, gff + (size_t)i * Dd, bff + (size_t)i * Dd, px);
    }

    copy_kernel<<<(Mm * Dd / 4) / 256, 256>>>(px, x_out);
}

// round 3
// speedup vs baseline: 1.3817x; 1.3817x over previous
#include <cuda_runtime.h>
#include <math.h>

// ---------------- problem constants ----------------
#define Bb 4
#define Ss 512
#define Dd 1024
#define Hh 16
#define DKk 64
#define DFFf 4096
#define Ll 6
#define Mm (Bb*Ss)      // 2048
#define BHh (Bb*Hh)     // 64

// ---------------- scratch (static device memory; no allocation) ----------------
__device__ float g_x[Mm*Dd];
__device__ float g_q[Mm*Dd];
__device__ float g_k[Mm*Dd];
__device__ float g_v[Mm*Dd];
__device__ float g_ctx[Mm*Dd];
__device__ float g_proj[Mm*Dd];
__device__ float g_scores[BHh*Ss*Ss];
__device__ float g_ffn[Mm*DFFf];

// ---------------- helpers ----------------
__device__ __forceinline__ unsigned tf32r(float x) {
    unsigned r; asm("cvt.rna.tf32.f32 %0, %1;" : "=r"(r) : "f"(x)); return r;
}

__device__ __forceinline__ void mma_m16n8k8(float4& d, const unsigned* a,
                                            unsigned b0, unsigned b1)
{
    asm volatile("mma.sync.aligned.m16n8k8.row.col.f32.tf32.tf32.f32 "
        "{%0,%1,%2,%3}, {%4,%5,%6,%7}, {%8,%9}, {%0,%1,%2,%3};"
        : "+f"(d.x), "+f"(d.y), "+f"(d.z), "+f"(d.w)
        : "r"(a[0]), "r"(a[1]), "r"(a[2]), "r"(a[3]), "r"(b0), "r"(b1));
}

// ---------------- embedding ----------------
__global__ void embed_kernel(const int* __restrict__ ids,
                             const float* __restrict__ tok,
                             const float* __restrict__ pos)
{
    int idx = blockIdx.x * blockDim.x + threadIdx.x;
    int row = idx >> 10;
    int d   = idx & (Dd - 1);
    int s   = row & (Ss - 1);
    g_x[idx] = tok[(size_t)ids[row] * Dd + d] + pos[(size_t)s * Dd + d];
}

// ---------------- 3xTF32 tensor-core GEMM: C = A[M,K] @ B[K,N] ----------------
// Block tile 128x128, K-chunk 16. 256 threads = 8 warps (2x4), warp tile 64x32.
// Each warp: 4x4 mma tiles of m16n8k8. hi/lo split staged once into smem.
#define BM 128
#define BN 128
#define BK 16

__global__ __launch_bounds__(256, 1) void mma_gemm_kernel(
    const float* __restrict__ A, const float* __restrict__ Bm,
    float* __restrict__ C, int N, int K, int relu)
{
    __shared__ unsigned As_h[BK][132];
    __shared__ unsigned As_l[BK][132];
    __shared__ unsigned Bs_h[BK][132];
    __shared__ unsigned Bs_l[BK][132];

    const int tid  = threadIdx.x;
    const int lane = tid & 31;
    const int warp = tid >> 5;
    const int wm   = warp >> 2;      // 0..1
    const int wn   = warp & 3;       // 0..3
    const int gid  = lane >> 2;      // 0..7
    const int tig  = lane & 3;       // 0..3

    const float* Aptr = A + (size_t)blockIdx.y * BM * K;
    const float* Bptr = Bm + blockIdx.x * BN;

    float4 acc[4][4];
    #pragma unroll
    for (int i = 0; i < 4; i++)
        #pragma unroll
        for (int j = 0; j < 4; j++)
            acc[i][j] = make_float4(0.f, 0.f, 0.f, 0.f);

    // staging register prefetch (chunk 0)
    float4 rA[2], rB[2];
    #pragma unroll
    for (int i = 0; i < 2; i++) {
        int f = tid + i * 256;                 // 0..511
        rA[i] = *(const float4*)(Aptr + (size_t)(f >> 2) * K + (f & 3) * 4);
        rB[i] = *(const float4*)(Bptr + (size_t)(f >> 5) * N + (f & 31) * 4);
    }

    const int nc = K / BK;
    for (int c = 0; c < nc; c++) {
        // ---- split & store chunk c into smem ----
        #pragma unroll
        for (int i = 0; i < 2; i++) {
            int f = tid + i * 256;
            int row = f >> 2, kg = f & 3;
            float va[4] = {rA[i].x, rA[i].y, rA[i].z, rA[i].w};
            #pragma unroll
            for (int j = 0; j < 4; j++) {
                unsigned h = tf32r(va[j]);
                float lo = va[j] - __uint_as_float(h);
                As_h[kg * 4 + j][row] = h;
                As_l[kg * 4 + j][row] = tf32r(lo);
            }
            int kr = f >> 5, n4 = (f & 31) * 4;
            float vb[4] = {rB[i].x, rB[i].y, rB[i].z, rB[i].w};
            unsigned bh4[4], bl4[4];
            #pragma unroll
            for (int j = 0; j < 4; j++) {
                bh4[j] = tf32r(vb[j]);
                float lo = vb[j] - __uint_as_float(bh4[j]);
                bl4[j] = tf32r(lo);
            }
            *(uint4*)&Bs_h[kr][n4] = make_uint4(bh4[0], bh4[1], bh4[2], bh4[3]);
            *(uint4*)&Bs_l[kr][n4] = make_uint4(bl4[0], bl4[1], bl4[2], bl4[3]);
        }
        __syncthreads();

        // ---- prefetch chunk c+1 (overlaps with compute below) ----
        if (c + 1 < nc) {
            #pragma unroll
            for (int i = 0; i < 2; i++) {
                int f = tid + i * 256;
                rA[i] = *(const float4*)(Aptr + (size_t)(f >> 2) * K + (c + 1) * BK + (f & 3) * 4);
                rB[i] = *(const float4*)(Bptr + (size_t)((c + 1) * BK + (f >> 5)) * N + (f & 31) * 4);
            }
        }

        // ---- compute: 2 k8 steps ----
        #pragma unroll
        for (int ks = 0; ks < 2; ks++) {
            const int kk = ks * 8;
            unsigned ah[4][4], al[4][4], bh[4][2], bl[4][2];
            #pragma unroll
            for (int mt = 0; mt < 4; mt++) {
                int r = wm * 64 + mt * 16 + gid;
                ah[mt][0] = As_h[kk + tig][r];
                ah[mt][1] = As_h[kk + tig][r + 8];
                ah[mt][2] = As_h[kk + tig + 4][r];
                ah[mt][3] = As_h[kk + tig + 4][r + 8];
                al[mt][0] = As_l[kk + tig][r];
                al[mt][1] = As_l[kk + tig][r + 8];
                al[mt][2] = As_l[kk + tig + 4][r];
                al[mt][3] = As_l[kk + tig + 4][r + 8];
            }
            #pragma unroll
            for (int nt = 0; nt < 4; nt++) {
                int nn = wn * 32 + nt * 8 + gid;
                bh[nt][0] = Bs_h[kk + tig][nn];
                bh[nt][1] = Bs_h[kk + tig + 4][nn];
                bl[nt][0] = Bs_l[kk + tig][nn];
                bl[nt][1] = Bs_l[kk + tig + 4][nn];
            }
            // 3 passes interleaved across 16 independent accumulators
            #pragma unroll
            for (int mt = 0; mt < 4; mt++)
                #pragma unroll
                for (int nt = 0; nt < 4; nt++)
                    mma_m16n8k8(acc[mt][nt], ah[mt], bh[nt][0], bh[nt][1]);
            #pragma unroll
            for (int mt = 0; mt < 4; mt++)
                #pragma unroll
                for (int nt = 0; nt < 4; nt++)
                    mma_m16n8k8(acc[mt][nt], ah[mt], bl[nt][0], bl[nt][1]);
            #pragma unroll
            for (int mt = 0; mt < 4; mt++)
                #pragma unroll
                for (int nt = 0; nt < 4; nt++)
                    mma_m16n8k8(acc[mt][nt], al[mt], bh[nt][0], bh[nt][1]);
        }
        __syncthreads();
    }

    // ---- epilogue ----
    #pragma unroll
    for (int mt = 0; mt < 4; mt++) {
        int row = blockIdx.y * BM + wm * 64 + mt * 16 + gid;
        #pragma unroll
        for (int nt = 0; nt < 4; nt++) {
            int col = blockIdx.x * BN + wn * 32 + nt * 8 + tig * 2;
            float2 v0 = make_float2(acc[mt][nt].x, acc[mt][nt].y);
            float2 v1 = make_float2(acc[mt][nt].z, acc[mt][nt].w);
            if (relu) {
                v0.x = fmaxf(v0.x, 0.f); v0.y = fmaxf(v0.y, 0.f);
                v1.x = fmaxf(v1.x, 0.f); v1.y = fmaxf(v1.y, 0.f);
            }
            *(float2*)(C + (size_t)row * N + col)       = v0;
            *(float2*)(C + (size_t)(row + 8) * N + col) = v1;
        }
    }
}

// ---------------- scores: S_bh[q,k] = (Q_bh . K_bh) / 8 ----------------
__global__ __launch_bounds__(256) void scores_kernel()
{
    __shared__ float Qs[64][65];
    __shared__ float Ks[64][65];
    int bh = blockIdx.z, b = bh >> 4, h = bh & 15;
    int q0 = blockIdx.y * 64, k0 = blockIdx.x * 64;
    int tid = threadIdx.x;
    int lr = tid >> 4, lc = (tid & 15) << 2;
    const float* Qb = g_q + ((size_t)b * Ss + q0) * Dd + h * DKk;
    const float* Kb = g_k + ((size_t)b * Ss + k0) * Dd + h * DKk;
    #pragma unroll
    for (int it = 0; it < 4; it++) {
        int r = lr + it * 16;
        float4 qv = *(const float4*)(Qb + (size_t)r * Dd + lc);
        Qs[r][lc] = qv.x; Qs[r][lc+1] = qv.y; Qs[r][lc+2] = qv.z; Qs[r][lc+3] = qv.w;
        float4 kv = *(const float4*)(Kb + (size_t)r * Dd + lc);
        Ks[r][lc] = kv.x; Ks[r][lc+1] = kv.y; Ks[r][lc+2] = kv.z; Ks[r][lc+3] = kv.w;
    }
    __syncthreads();
    int ty = tid >> 4, tx = tid & 15;
    float acc[4][4] = {};
    #pragma unroll
    for (int kk = 0; kk < 64; kk++) {
        float ar[4], br[4];
        #pragma unroll
        for (int i = 0; i < 4; i++) ar[i] = Qs[ty * 4 + i][kk];
        #pragma unroll
        for (int j = 0; j < 4; j++) br[j] = Ks[tx * 4 + j][kk];
        #pragma unroll
        for (int i = 0; i < 4; i++)
            #pragma unroll
            for (int j = 0; j < 4; j++)
                acc[i][j] = fmaf(ar[i], br[j], acc[i][j]);
    }
    float* out = g_scores + ((size_t)bh * Ss + q0 + ty * 4) * Ss + k0 + tx * 4;
    #pragma unroll
    for (int i = 0; i < 4; i++)
        #pragma unroll
        for (int j = 0; j < 4; j++)
            out[(size_t)i * Ss + j] = acc[i][j] * 0.125f;
}

// ---------------- fused mask + softmax over k (row length 512) ----------------
__global__ __launch_bounds__(256) void softmax_kernel(
    const float* __restrict__ src, float* __restrict__ dst,
    const int* __restrict__ ids, int masked)
{
    __shared__ float sh[8];
    int bhq = blockIdx.x;
    int q = bhq & (Ss - 1);
    int b = bhq >> 13;
    const float* row = src + (size_t)bhq * Ss;
    float* orow = dst + (size_t)bhq * Ss;
    int tid = threadIdx.x;

    int k0 = tid, k1 = tid + 256;
    float v0 = row[k0], v1 = row[k1];
    if (masked) {
        if (k0 > q || ids[b * Ss + k0] == 0) v0 = -1e9f;
        if (k1 > q || ids[b * Ss + k1] == 0) v1 = -1e9f;
    }
    float m = fmaxf(v0, v1);
    #pragma unroll
    for (int o = 16; o; o >>= 1) m = fmaxf(m, __shfl_xor_sync(0xffffffffu, m, o));
    if ((tid & 31) == 0) sh[tid >> 5] = m;
    __syncthreads();
    m = sh[0];
    #pragma unroll
    for (int w = 1; w < 8; w++) m = fmaxf(m, sh[w]);

    float e0 = expf(v0 - m), e1 = expf(v1 - m);
    float s = e0 + e1;
    #pragma unroll
    for (int o = 16; o; o >>= 1) s += __shfl_xor_sync(0xffffffffu, s, o);
    __syncthreads();
    if ((tid & 31) == 0) sh[tid >> 5] = s;
    __syncthreads();
    s = 0.f;
    #pragma unroll
    for (int w = 0; w < 8; w++) s += sh[w];
    float inv = 1.0f / s;
    orow[k0] = e0 * inv;
    orow[k1] = e1 * inv;
}

// ---------------- ctx: C_bh[q,d] = P_bh[q,:] @ V_bh[:,d] ----------------
__global__ __launch_bounds__(256) void ctx_kernel(const float* __restrict__ P)
{
    __shared__ float Ps[64][33];
    __shared__ float Vs[32][65];
    int bh = blockIdx.z, b = bh >> 4, h = bh & 15;
    int q0 = blockIdx.x * 64;
    int tid = threadIdx.x;
    const float* Pb = P + ((size_t)bh * Ss + q0) * Ss;
    const float* Vb = g_v + (size_t)b * Ss * Dd + h * DKk;
    int pr = tid >> 3, pc = (tid & 7) << 2;
    int vr = tid >> 4, vc = (tid & 15) << 2;
    int ty = tid >> 4, tx = tid & 15;
    float acc[4][4] = {};
    for (int kb = 0; kb < Ss; kb += 32) {
        #pragma unroll
        for (int it = 0; it < 2; it++) {
            int r = pr + it * 32;
            float4 pv = *(const float4*)(Pb + (size_t)r * Ss + kb + pc);
            Ps[r][pc] = pv.x; Ps[r][pc+1] = pv.y; Ps[r][pc+2] = pv.z; Ps[r][pc+3] = pv.w;
            int r2 = vr + it * 16;
            float4 vv = *(const float4*)(Vb + (size_t)(kb + r2) * Dd + vc);
            Vs[r2][vc] = vv.x; Vs[r2][vc+1] = vv.y; Vs[r2][vc+2] = vv.z; Vs[r2][vc+3] = vv.w;
        }
        __syncthreads();
        #pragma unroll
        for (int kk = 0; kk < 32; kk++) {
            float ar[4], br[4];
            #pragma unroll
            for (int i = 0; i < 4; i++) ar[i] = Ps[ty * 4 + i][kk];
            #pragma unroll
            for (int j = 0; j < 4; j++) br[j] = Vs[kk][tx * 4 + j];
            #pragma unroll
            for (int i = 0; i < 4; i++)
                #pragma unroll
                for (int j = 0; j < 4; j++)
                    acc[i][j] = fmaf(ar[i], br[j], acc[i][j]);
        }
        __syncthreads();
    }
    float* out = g_ctx + ((size_t)b * Ss + q0 + ty * 4) * Dd + h * DKk + tx * 4;
    #pragma unroll
    for (int i = 0; i < 4; i++)
        #pragma unroll
        for (int j = 0; j < 4; j++)
            out[(size_t)i * Dd + j] = acc[i][j];
}

// ---------------- fused residual + LayerNorm (row = 1024) ----------------
__global__ __launch_bounds__(256) void ln_kernel(
    const float* __restrict__ hb, const float* __restrict__ res,
    const float* __restrict__ g, const float* __restrict__ bta,
    float* __restrict__ out)
{
    __shared__ float sh[8];
    int row = blockIdx.x, tid = threadIdx.x;
    const float* hr = hb + (size_t)row * Dd;
    const float* rr = res + (size_t)row * Dd;
    float v[4];
    #pragma unroll
    for (int i = 0; i < 4; i++) v[i] = hr[tid + i * 256] + rr[tid + i * 256];

    float s = v[0] + v[1] + v[2] + v[3];
    #pragma unroll
    for (int o = 16; o; o >>= 1) s += __shfl_xor_sync(0xffffffffu, s, o);
    if ((tid & 31) == 0) sh[tid >> 5] = s;
    __syncthreads();
    s = 0.f;
    #pragma unroll
    for (int w = 0; w < 8; w++) s += sh[w];
    float mean = s * (1.0f / Dd);

    float qs = 0.f;
    #pragma unroll
    for (int i = 0; i < 4; i++) { float d0 = v[i] - mean; qs = fmaf(d0, d0, qs); }
    #pragma unroll
    for (int o = 16; o; o >>= 1) qs += __shfl_xor_sync(0xffffffffu, qs, o);
    __syncthreads();
    if ((tid & 31) == 0) sh[tid >> 5] = qs;
    __syncthreads();
    qs = 0.f;
    #pragma unroll
    for (int w = 0; w < 8; w++) qs += sh[w];
    float var = qs * (1.0f / Dd);
    float scale = rsqrtf(var + 1e-5f);

    #pragma unroll
    for (int i = 0; i < 4; i++) {
        int c = tid + i * 256;
        out[(size_t)row * Dd + c] = (v[i] - mean) * scale * g[c] + bta[c];
    }
}

__global__ void copy_kernel(const float* __restrict__ src, float* __restrict__ dst)
{
    int i = blockIdx.x * blockDim.x + threadIdx.x;
    ((float4*)dst)[i] = ((const float4*)src)[i];
}

// ---------------- host orchestration ----------------
extern "C" void kernel_launch(void* const* d_in, const int* in_sizes, int n_in,
                              void* d_out, int out_size)
{
    (void)in_sizes; (void)n_in; (void)out_size;
    const int*   ids  = (const int*)  d_in[0];
    const float* tok  = (const float*)d_in[1];
    const float* pos  = (const float*)d_in[2];
    const float* Wq1  = (const float*)d_in[3];
    const float* Wk1  = (const float*)d_in[4];
    const float* Wv1  = (const float*)d_in[5];
    const float* Wo1  = (const float*)d_in[6];
    const float* g1   = (const float*)d_in[7];
    const float* b1   = (const float*)d_in[8];
    const float* Wq2  = (const float*)d_in[9];
    const float* Wk2  = (const float*)d_in[10];
    const float* Wv2  = (const float*)d_in[11];
    const float* Wo2  = (const float*)d_in[12];
    const float* g2   = (const float*)d_in[13];
    const float* b2   = (const float*)d_in[14];
    const float* Wff1 = (const float*)d_in[15];
    const float* Wff2 = (const float*)d_in[16];
    const float* gff  = (const float*)d_in[17];
    const float* bff  = (const float*)d_in[18];

    float* out = (float*)d_out;
    float* x_out = out;
    float* attn_out = out + (size_t)Mm * Dd;

    float *px, *pq, *pk, *pv, *pctx, *pproj, *pscores, *pffn;
    cudaGetSymbolAddress((void**)&px,     g_x);
    cudaGetSymbolAddress((void**)&pq,     g_q);
    cudaGetSymbolAddress((void**)&pk,     g_k);
    cudaGetSymbolAddress((void**)&pv,     g_v);
    cudaGetSymbolAddress((void**)&pctx,   g_ctx);
    cudaGetSymbolAddress((void**)&pproj,  g_proj);
    cudaGetSymbolAddress((void**)&pscores,g_scores);
    cudaGetSymbolAddress((void**)&pffn,   g_ffn);

    embed_kernel<<<(Mm * Dd) / 256, 256>>>(ids, tok, pos);

    const dim3 gProj(Dd / BN, Mm / BM);       // 8 x 16
    const dim3 gFfn1(DFFf / BN, Mm / BM);     // 32 x 16
    const dim3 gScores(8, 8, BHh);
    const dim3 gCtx(8, 1, BHh);

    for (int i = 0; i < Ll; i++) {
        // ---- MHA1 (masked self-attn, attn not output) ----
        mma_gemm_kernel<<<gProj, 256>>>(px, Wq1 + (size_t)i * Dd * Dd, pq, Dd, Dd, 0);
        mma_gemm_kernel<<<gProj, 256>>>(px, Wk1 + (size_t)i * Dd * Dd, pk, Dd, Dd, 0);
        mma_gemm_kernel<<<gProj, 256>>>(px, Wv1 + (size_t)i * Dd * Dd, pv, Dd, Dd, 0);
        scores_kernel<<<gScores, 256>>>();
        softmax_kernel<<<BHh * Ss, 256>>>(pscores, pscores, ids, 1);
        ctx_kernel<<<gCtx, 256>>>(pscores);
        mma_gemm_kernel<<<gProj, 256>>>(pctx, Wo1 + (size_t)i * Dd * Dd, pproj, Dd, Dd, 0);
        ln_kernel<<<Mm, 256>>>(pproj, px, g1 + (size_t)i * Dd, b1 + (size_t)i * Dd, px);

        // ---- MHA2 (no mask; attn written to output) ----
        float* attn_i = attn_out + (size_t)i * BHh * Ss * Ss;
        mma_gemm_kernel<<<gProj, 256>>>(px, Wq2 + (size_t)i * Dd * Dd, pq, Dd, Dd, 0);
        mma_gemm_kernel<<<gProj, 256>>>(px, Wk2 + (size_t)i * Dd * Dd, pk, Dd, Dd, 0);
        mma_gemm_kernel<<<gProj, 256>>>(px, Wv2 + (size_t)i * Dd * Dd, pv, Dd, Dd, 0);
        scores_kernel<<<gScores, 256>>>();
        softmax_kernel<<<BHh * Ss, 256>>>(pscores, attn_i, ids, 0);
        ctx_kernel<<<gCtx, 256>>>(attn_i);
        mma_gemm_kernel<<<gProj, 256>>>(pctx, Wo2 + (size_t)i * Dd * Dd, pproj, Dd, Dd, 0);
        ln_kernel<<<Mm, 256>>>(pproj, px, g2 + (size_t)i * Dd, b2 + (size_t)i * Dd, px);

        // ---- FFN ----
        mma_gemm_kernel<<<gFfn1, 256>>>(px, Wff1 + (size_t)i * Dd * DFFf, pffn, DFFf, Dd, 1);
        mma_gemm_kernel<<<gProj, 256>>>(pffn, Wff2 + (size_t)i * DFFf * Dd, pproj, Dd, DFFf, 0);
        ln_kernel<<<Mm, 256>>>(pproj, px, gff + (size_t)i * Dd, bff + (size_t)i * Dd, px);
    }

    copy_kernel<<<(Mm * Dd / 4) / 256, 256>>>(px, x_out);
}

// round 4
// speedup vs baseline: 1.5484x; 1.1206x over previous
#include <cuda_runtime.h>
#include <math.h>

// ---------------- problem constants ----------------
#define Bb 4
#define Ss 512
#define Dd 1024
#define Hh 16
#define DKk 64
#define DFFf 4096
#define Ll 6
#define Mm (Bb*Ss)      // 2048
#define BHh (Bb*Hh)     // 64

// ---------------- scratch (static device memory; no allocation) ----------------
__device__ float g_x[Mm*Dd];
__device__ float g_q[Mm*Dd];
__device__ float g_k[Mm*Dd];
__device__ float g_v[Mm*Dd];
__device__ float g_ctx[Mm*Dd];
__device__ float g_proj[Mm*Dd];
__device__ float g_scores[BHh*Ss*Ss];
__device__ float g_ffn[Mm*DFFf];

// ---------------- helpers ----------------
__device__ __forceinline__ unsigned tf32r(float x) {
    unsigned r; asm("cvt.rna.tf32.f32 %0, %1;" : "=r"(r) : "f"(x)); return r;
}

__device__ __forceinline__ void mma_m16n8k8(float4& d, const unsigned* a,
                                            unsigned b0, unsigned b1)
{
    asm volatile("mma.sync.aligned.m16n8k8.row.col.f32.tf32.tf32.f32 "
        "{%0,%1,%2,%3}, {%4,%5,%6,%7}, {%8,%9}, {%0,%1,%2,%3};"
        : "+f"(d.x), "+f"(d.y), "+f"(d.z), "+f"(d.w)
        : "r"(a[0]), "r"(a[1]), "r"(a[2]), "r"(a[3]), "r"(b0), "r"(b1));
}

// ---------------- embedding ----------------
__global__ void embed_kernel(const int* __restrict__ ids,
                             const float* __restrict__ tok,
                             const float* __restrict__ pos)
{
    int idx = blockIdx.x * blockDim.x + threadIdx.x;
    int row = idx >> 10;
    int d   = idx & (Dd - 1);
    int s   = row & (Ss - 1);
    g_x[idx] = tok[(size_t)ids[row] * Dd + d] + pos[(size_t)s * Dd + d];
}

// ---------------- 3xTF32 tensor-core GEMM: C = A[M,K] @ B[K,N] ----------------
// 512 threads = 16 warps (4x4), warp tile 32x32, block tile 128x128, BK=16.
// Double-buffered dynamic smem; hi/lo tf32 split staged once per chunk.
// blockIdx.z selects among up to 3 (B,C) pairs (fused QKV).
#define BM 128
#define BN 128
#define BK 16
#define PAD 136
#define STAGE_U (4*BK*PAD)                 // 4 arrays per stage, in unsigneds
#define GEMM_SMEM_BYTES (2*STAGE_U*4)      // 69632 bytes

__global__ __launch_bounds__(512) void mma_gemm_kernel(
    const float* __restrict__ A,
    const float* __restrict__ Bp0, const float* __restrict__ Bp1,
    const float* __restrict__ Bp2,
    float* __restrict__ Cp0, float* __restrict__ Cp1, float* __restrict__ Cp2,
    int N, int K, int relu)
{
    extern __shared__ unsigned smx[];

    const float* Bm = (blockIdx.z == 0) ? Bp0 : ((blockIdx.z == 1) ? Bp1 : Bp2);
    float*       C  = (blockIdx.z == 0) ? Cp0 : ((blockIdx.z == 1) ? Cp1 : Cp2);

    const int tid  = threadIdx.x;
    const int lane = tid & 31;
    const int warp = tid >> 5;
    const int wm   = warp >> 2;      // 0..3
    const int wn   = warp & 3;       // 0..3
    const int gid  = lane >> 2;      // 0..7
    const int tig  = lane & 3;       // 0..3

    const float* Aptr = A  + (size_t)blockIdx.y * BM * K;
    const float* Bptr = Bm + blockIdx.x * BN;

    // loader indices: A chunk 128x16 = 512 float4; B chunk 16x128 = 512 float4
    const int a_row = tid >> 2;       // 0..127
    const int a_kg  = tid & 3;        // float4 index along k
    const int b_kr  = tid >> 5;       // 0..15
    const int b_c4  = tid & 31;       // float4 col

    float4 acc[2][4];
    #pragma unroll
    for (int i = 0; i < 2; i++)
        #pragma unroll
        for (int j = 0; j < 4; j++) acc[i][j] = make_float4(0.f,0.f,0.f,0.f);

    float4 rA, rB;

    const int nc = K / BK;

    // ---- prologue: chunk0 -> smem[0], prefetch chunk1 ----
    rA = *(const float4*)(Aptr + (size_t)a_row * K + a_kg * 4);
    rB = *(const float4*)(Bptr + (size_t)b_kr * N + b_c4 * 4);
    {
        unsigned* As_h = smx;
        unsigned* As_l = As_h + BK*PAD;
        unsigned* Bs_h = As_l + BK*PAD;
        unsigned* Bs_l = Bs_h + BK*PAD;
        float va[4] = {rA.x, rA.y, rA.z, rA.w};
        #pragma unroll
        for (int j = 0; j < 4; j++) {
            unsigned h = tf32r(va[j]);
            As_h[(a_kg*4 + j)*PAD + a_row] = h;
            As_l[(a_kg*4 + j)*PAD + a_row] = tf32r(va[j] - __uint_as_float(h));
        }
        float vb[4] = {rB.x, rB.y, rB.z, rB.w};
        unsigned sh4[4], sl4[4];
        #pragma unroll
        for (int j = 0; j < 4; j++) {
            sh4[j] = tf32r(vb[j]);
            sl4[j] = tf32r(vb[j] - __uint_as_float(sh4[j]));
        }
        *(uint4*)&Bs_h[b_kr*PAD + b_c4*4] = make_uint4(sh4[0],sh4[1],sh4[2],sh4[3]);
        *(uint4*)&Bs_l[b_kr*PAD + b_c4*4] = make_uint4(sl4[0],sl4[1],sl4[2],sl4[3]);
    }
    if (nc > 1) {
        rA = *(const float4*)(Aptr + (size_t)a_row * K + BK + a_kg * 4);
        rB = *(const float4*)(Bptr + (size_t)(BK + b_kr) * N + b_c4 * 4);
    }
    __syncthreads();

    for (int c = 0; c < nc; c++) {
        // ---- compute on stage c&1 ----
        {
            unsigned* As_h = smx + (c & 1) * STAGE_U;
            unsigned* As_l = As_h + BK*PAD;
            unsigned* Bs_h = As_l + BK*PAD;
            unsigned* Bs_l = Bs_h + BK*PAD;
            #pragma unroll
            for (int ks = 0; ks < 2; ks++) {
                const int kk = ks * 8;
                unsigned ah[2][4], al[2][4], bh[4][2], bl[4][2];
                #pragma unroll
                for (int mt = 0; mt < 2; mt++) {
                    int r = wm * 32 + mt * 16 + gid;
                    ah[mt][0] = As_h[(kk + tig)*PAD + r];
                    ah[mt][1] = As_h[(kk + tig)*PAD + r + 8];
                    ah[mt][2] = As_h[(kk + tig + 4)*PAD + r];
                    ah[mt][3] = As_h[(kk + tig + 4)*PAD + r + 8];
                    al[mt][0] = As_l[(kk + tig)*PAD + r];
                    al[mt][1] = As_l[(kk + tig)*PAD + r + 8];
                    al[mt][2] = As_l[(kk + tig + 4)*PAD + r];
                    al[mt][3] = As_l[(kk + tig + 4)*PAD + r + 8];
                }
                #pragma unroll
                for (int nt = 0; nt < 4; nt++) {
                    int nn = wn * 32 + nt * 8 + gid;
                    bh[nt][0] = Bs_h[(kk + tig)*PAD + nn];
                    bh[nt][1] = Bs_h[(kk + tig + 4)*PAD + nn];
                    bl[nt][0] = Bs_l[(kk + tig)*PAD + nn];
                    bl[nt][1] = Bs_l[(kk + tig + 4)*PAD + nn];
                }
                #pragma unroll
                for (int mt = 0; mt < 2; mt++)
                    #pragma unroll
                    for (int nt = 0; nt < 4; nt++)
                        mma_m16n8k8(acc[mt][nt], ah[mt], bh[nt][0], bh[nt][1]);
                #pragma unroll
                for (int mt = 0; mt < 2; mt++)
                    #pragma unroll
                    for (int nt = 0; nt < 4; nt++)
                        mma_m16n8k8(acc[mt][nt], ah[mt], bl[nt][0], bl[nt][1]);
                #pragma unroll
                for (int mt = 0; mt < 2; mt++)
                    #pragma unroll
                    for (int nt = 0; nt < 4; nt++)
                        mma_m16n8k8(acc[mt][nt], al[mt], bh[nt][0], bh[nt][1]);
            }
        }

        // ---- split+store chunk c+1 into the other stage ----
        if (c + 1 < nc) {
            unsigned* As_h = smx + ((c + 1) & 1) * STAGE_U;
            unsigned* As_l = As_h + BK*PAD;
            unsigned* Bs_h = As_l + BK*PAD;
            unsigned* Bs_l = Bs_h + BK*PAD;
            float va[4] = {rA.x, rA.y, rA.z, rA.w};
            #pragma unroll
            for (int j = 0; j < 4; j++) {
                unsigned h = tf32r(va[j]);
                As_h[(a_kg*4 + j)*PAD + a_row] = h;
                As_l[(a_kg*4 + j)*PAD + a_row] = tf32r(va[j] - __uint_as_float(h));
            }
            float vb[4] = {rB.x, rB.y, rB.z, rB.w};
            unsigned sh4[4], sl4[4];
            #pragma unroll
            for (int j = 0; j < 4; j++) {
                sh4[j] = tf32r(vb[j]);
                sl4[j] = tf32r(vb[j] - __uint_as_float(sh4[j]));
            }
            *(uint4*)&Bs_h[b_kr*PAD + b_c4*4] = make_uint4(sh4[0],sh4[1],sh4[2],sh4[3]);
            *(uint4*)&Bs_l[b_kr*PAD + b_c4*4] = make_uint4(sl4[0],sl4[1],sl4[2],sl4[3]);
        }
        // ---- prefetch chunk c+2 ----
        if (c + 2 < nc) {
            rA = *(const float4*)(Aptr + (size_t)a_row * K + (c + 2) * BK + a_kg * 4);
            rB = *(const float4*)(Bptr + (size_t)((c + 2) * BK + b_kr) * N + b_c4 * 4);
        }
        __syncthreads();
    }

    // ---- epilogue ----
    #pragma unroll
    for (int mt = 0; mt < 2; mt++) {
        int row = blockIdx.y * BM + wm * 32 + mt * 16 + gid;
        #pragma unroll
        for (int nt = 0; nt < 4; nt++) {
            int col = blockIdx.x * BN + wn * 32 + nt * 8 + tig * 2;
            float2 v0 = make_float2(acc[mt][nt].x, acc[mt][nt].y);
            float2 v1 = make_float2(acc[mt][nt].z, acc[mt][nt].w);
            if (relu) {
                v0.x = fmaxf(v0.x, 0.f); v0.y = fmaxf(v0.y, 0.f);
                v1.x = fmaxf(v1.x, 0.f); v1.y = fmaxf(v1.y, 0.f);
            }
            *(float2*)(C + (size_t)row * N + col)       = v0;
            *(float2*)(C + (size_t)(row + 8) * N + col) = v1;
        }
    }
}

// ---------------- scores: S_bh[q,k] = (Q_bh . K_bh) / 8 ----------------
__global__ __launch_bounds__(256) void scores_kernel()
{
    __shared__ float Qs[64][65];
    __shared__ float Ks[64][65];
    int bh = blockIdx.z, b = bh >> 4, h = bh & 15;
    int q0 = blockIdx.y * 64, k0 = blockIdx.x * 64;
    int tid = threadIdx.x;
    int lr = tid >> 4, lc = (tid & 15) << 2;
    const float* Qb = g_q + ((size_t)b * Ss + q0) * Dd + h * DKk;
    const float* Kb = g_k + ((size_t)b * Ss + k0) * Dd + h * DKk;
    #pragma unroll
    for (int it = 0; it < 4; it++) {
        int r = lr + it * 16;
        float4 qv = *(const float4*)(Qb + (size_t)r * Dd + lc);
        Qs[r][lc] = qv.x; Qs[r][lc+1] = qv.y; Qs[r][lc+2] = qv.z; Qs[r][lc+3] = qv.w;
        float4 kv = *(const float4*)(Kb + (size_t)r * Dd + lc);
        Ks[r][lc] = kv.x; Ks[r][lc+1] = kv.y; Ks[r][lc+2] = kv.z; Ks[r][lc+3] = kv.w;
    }
    __syncthreads();
    int ty = tid >> 4, tx = tid & 15;
    float acc[4][4] = {};
    #pragma unroll
    for (int kk = 0; kk < 64; kk++) {
        float ar[4], br[4];
        #pragma unroll
        for (int i = 0; i < 4; i++) ar[i] = Qs[ty * 4 + i][kk];
        #pragma unroll
        for (int j = 0; j < 4; j++) br[j] = Ks[tx * 4 + j][kk];
        #pragma unroll
        for (int i = 0; i < 4; i++)
            #pragma unroll
            for (int j = 0; j < 4; j++)
                acc[i][j] = fmaf(ar[i], br[j], acc[i][j]);
    }
    float* out = g_scores + ((size_t)bh * Ss + q0 + ty * 4) * Ss + k0 + tx * 4;
    #pragma unroll
    for (int i = 0; i < 4; i++)
        #pragma unroll
        for (int j = 0; j < 4; j++)
            out[(size_t)i * Ss + j] = acc[i][j] * 0.125f;
}

// ---------------- fused mask + softmax over k (row length 512) ----------------
__global__ __launch_bounds__(256) void softmax_kernel(
    const float* __restrict__ src, float* __restrict__ dst,
    const int* __restrict__ ids, int masked)
{
    __shared__ float sh[8];
    int bhq = blockIdx.x;
    int q = bhq & (Ss - 1);
    int b = bhq >> 13;
    const float* row = src + (size_t)bhq * Ss;
    float* orow = dst + (size_t)bhq * Ss;
    int tid = threadIdx.x;

    int k0 = tid, k1 = tid + 256;
    float v0 = row[k0], v1 = row[k1];
    if (masked) {
        if (k0 > q || ids[b * Ss + k0] == 0) v0 = -1e9f;
        if (k1 > q || ids[b * Ss + k1] == 0) v1 = -1e9f;
    }
    float m = fmaxf(v0, v1);
    #pragma unroll
    for (int o = 16; o; o >>= 1) m = fmaxf(m, __shfl_xor_sync(0xffffffffu, m, o));
    if ((tid & 31) == 0) sh[tid >> 5] = m;
    __syncthreads();
    m = sh[0];
    #pragma unroll
    for (int w = 1; w < 8; w++) m = fmaxf(m, sh[w]);

    float e0 = expf(v0 - m), e1 = expf(v1 - m);
    float s = e0 + e1;
    #pragma unroll
    for (int o = 16; o; o >>= 1) s += __shfl_xor_sync(0xffffffffu, s, o);
    __syncthreads();
    if ((tid & 31) == 0) sh[tid >> 5] = s;
    __syncthreads();
    s = 0.f;
    #pragma unroll
    for (int w = 0; w < 8; w++) s += sh[w];
    float inv = 1.0f / s;
    orow[k0] = e0 * inv;
    orow[k1] = e1 * inv;
}

// ---------------- ctx: C_bh[q,d] = P_bh[q,:] @ V_bh[:,d] ----------------
__global__ __launch_bounds__(256) void ctx_kernel(const float* __restrict__ P)
{
    __shared__ float Ps[64][33];
    __shared__ float Vs[32][65];
    int bh = blockIdx.z, b = bh >> 4, h = bh & 15;
    int q0 = blockIdx.x * 64;
    int tid = threadIdx.x;
    const float* Pb = P + ((size_t)bh * Ss + q0) * Ss;
    const float* Vb = g_v + (size_t)b * Ss * Dd + h * DKk;
    int pr = tid >> 3, pc = (tid & 7) << 2;
    int vr = tid >> 4, vc = (tid & 15) << 2;
    int ty = tid >> 4, tx = tid & 15;
    float acc[4][4] = {};
    for (int kb = 0; kb < Ss; kb += 32) {
        #pragma unroll
        for (int it = 0; it < 2; it++) {
            int r = pr + it * 32;
            float4 pv = *(const float4*)(Pb + (size_t)r * Ss + kb + pc);
            Ps[r][pc] = pv.x; Ps[r][pc+1] = pv.y; Ps[r][pc+2] = pv.z; Ps[r][pc+3] = pv.w;
            int r2 = vr + it * 16;
            float4 vv = *(const float4*)(Vb + (size_t)(kb + r2) * Dd + vc);
            Vs[r2][vc] = vv.x; Vs[r2][vc+1] = vv.y; Vs[r2][vc+2] = vv.z; Vs[r2][vc+3] = vv.w;
        }
        __syncthreads();
        #pragma unroll
        for (int kk = 0; kk < 32; kk++) {
            float ar[4], br[4];
            #pragma unroll
            for (int i = 0; i < 4; i++) ar[i] = Ps[ty * 4 + i][kk];
            #pragma unroll
            for (int j = 0; j < 4; j++) br[j] = Vs[kk][tx * 4 + j];
            #pragma unroll
            for (int i = 0; i < 4; i++)
                #pragma unroll
                for (int j = 0; j < 4; j++)
                    acc[i][j] = fmaf(ar[i], br[j], acc[i][j]);
        }
        __syncthreads();
    }
    float* out = g_ctx + ((size_t)b * Ss + q0 + ty * 4) * Dd + h * DKk + tx * 4;
    #pragma unroll
    for (int i = 0; i < 4; i++)
        #pragma unroll
        for (int j = 0; j < 4; j++)
            out[(size_t)i * Dd + j] = acc[i][j];
}

// ---------------- fused residual + LayerNorm (row = 1024) ----------------
__global__ __launch_bounds__(256) void ln_kernel(
    const float* __restrict__ hb, const float* __restrict__ res,
    const float* __restrict__ g, const float* __restrict__ bta,
    float* __restrict__ out)
{
    __shared__ float sh[8];
    int row = blockIdx.x, tid = threadIdx.x;
    const float* hr = hb + (size_t)row * Dd;
    const float* rr = res + (size_t)row * Dd;
    float v[4];
    #pragma unroll
    for (int i = 0; i < 4; i++) v[i] = hr[tid + i * 256] + rr[tid + i * 256];

    float s = v[0] + v[1] + v[2] + v[3];
    #pragma unroll
    for (int o = 16; o; o >>= 1) s += __shfl_xor_sync(0xffffffffu, s, o);
    if ((tid & 31) == 0) sh[tid >> 5] = s;
    __syncthreads();
    s = 0.f;
    #pragma unroll
    for (int w = 0; w < 8; w++) s += sh[w];
    float mean = s * (1.0f / Dd);

    float qs = 0.f;
    #pragma unroll
    for (int i = 0; i < 4; i++) { float d0 = v[i] - mean; qs = fmaf(d0, d0, qs); }
    #pragma unroll
    for (int o = 16; o; o >>= 1) qs += __shfl_xor_sync(0xffffffffu, qs, o);
    __syncthreads();
    if ((tid & 31) == 0) sh[tid >> 5] = qs;
    __syncthreads();
    qs = 0.f;
    #pragma unroll
    for (int w = 0; w < 8; w++) qs += sh[w];
    float var = qs * (1.0f / Dd);
    float scale = rsqrtf(var + 1e-5f);

    #pragma unroll
    for (int i = 0; i < 4; i++) {
        int c = tid + i * 256;
        out[(size_t)row * Dd + c] = (v[i] - mean) * scale * g[c] + bta[c];
    }
}

__global__ void copy_kernel(const float* __restrict__ src, float* __restrict__ dst)
{
    int i = blockIdx.x * blockDim.x + threadIdx.x;
    ((float4*)dst)[i] = ((const float4*)src)[i];
}

// ---------------- host orchestration ----------------
extern "C" void kernel_launch(void* const* d_in, const int* in_sizes, int n_in,
                              void* d_out, int out_size)
{
    (void)in_sizes; (void)n_in; (void)out_size;
    const int*   ids  = (const int*)  d_in[0];
    const float* tok  = (const float*)d_in[1];
    const float* pos  = (const float*)d_in[2];
    const float* Wq1  = (const float*)d_in[3];
    const float* Wk1  = (const float*)d_in[4];
    const float* Wv1  = (const float*)d_in[5];
    const float* Wo1  = (const float*)d_in[6];
    const float* g1   = (const float*)d_in[7];
    const float* b1   = (const float*)d_in[8];
    const float* Wq2  = (const float*)d_in[9];
    const float* Wk2  = (const float*)d_in[10];
    const float* Wv2  = (const float*)d_in[11];
    const float* Wo2  = (const float*)d_in[12];
    const float* g2   = (const float*)d_in[13];
    const float* b2   = (const float*)d_in[14];
    const float* Wff1 = (const float*)d_in[15];
    const float* Wff2 = (const float*)d_in[16];
    const float* gff  = (const float*)d_in[17];
    const float* bff  = (const float*)d_in[18];

    float* out = (float*)d_out;
    float* x_out = out;
    float* attn_out = out + (size_t)Mm * Dd;

    float *px, *pq, *pk, *pv, *pctx, *pproj, *pscores, *pffn;
    cudaGetSymbolAddress((void**)&px,     g_x);
    cudaGetSymbolAddress((void**)&pq,     g_q);
    cudaGetSymbolAddress((void**)&pk,     g_k);
    cudaGetSymbolAddress((void**)&pv,     g_v);
    cudaGetSymbolAddress((void**)&pctx,   g_ctx);
    cudaGetSymbolAddress((void**)&pproj,  g_proj);
    cudaGetSymbolAddress((void**)&pscores,g_scores);
    cudaGetSymbolAddress((void**)&pffn,   g_ffn);

    cudaFuncSetAttribute(mma_gemm_kernel,
                         cudaFuncAttributeMaxDynamicSharedMemorySize,
                         GEMM_SMEM_BYTES);

    embed_kernel<<<(Mm * Dd) / 256, 256>>>(ids, tok, pos);

    const dim3 gQKV (Dd / BN, Mm / BM, 3);    // fused Q,K,V
    const dim3 gProj(Dd / BN, Mm / BM, 1);
    const dim3 gFfn1(DFFf / BN, Mm / BM, 1);
    const dim3 gScores(8, 8, BHh);
    const dim3 gCtx(8, 1, BHh);

    for (int i = 0; i < Ll; i++) {
        // ---- MHA1 (masked self-attn, attn not output) ----
        mma_gemm_kernel<<<gQKV, 512, GEMM_SMEM_BYTES>>>(px,
            Wq1 + (size_t)i * Dd * Dd, Wk1 + (size_t)i * Dd * Dd, Wv1 + (size_t)i * Dd * Dd,
            pq, pk, pv, Dd, Dd, 0);
        scores_kernel<<<gScores, 256>>>();
        softmax_kernel<<<BHh * Ss, 256>>>(pscores, pscores, ids, 1);
        ctx_kernel<<<gCtx, 256>>>(pscores);
        mma_gemm_kernel<<<gProj, 512, GEMM_SMEM_BYTES>>>(pctx,
            Wo1 + (size_t)i * Dd * Dd, Wo1, Wo1, pproj, pproj, pproj, Dd, Dd, 0);
        ln_kernel<<<Mm, 256>>>(pproj, px, g1 + (size_t)i * Dd, b1 + (size_t)i * Dd, px);

        // ---- MHA2 (no mask; attn written to output) ----
        float* attn_i = attn_out + (size_t)i * BHh * Ss * Ss;
        mma_gemm_kernel<<<gQKV, 512, GEMM_SMEM_BYTES>>>(px,
            Wq2 + (size_t)i * Dd * Dd, Wk2 + (size_t)i * Dd * Dd, Wv2 + (size_t)i * Dd * Dd,
            pq, pk, pv, Dd, Dd, 0);
        scores_kernel<<<gScores, 256>>>();
        softmax_kernel<<<BHh * Ss, 256>>>(pscores, attn_i, ids, 0);
        ctx_kernel<<<gCtx, 256>>>(attn_i);
        mma_gemm_kernel<<<gProj, 512, GEMM_SMEM_BYTES>>>(pctx,
            Wo2 + (size_t)i * Dd * Dd, Wo2, Wo2, pproj, pproj, pproj, Dd, Dd, 0);
        ln_kernel<<<Mm, 256>>>(pproj, px, g2 + (size_t)i * Dd, b2 + (size_t)i * Dd, px);

        // ---- FFN ----
        mma_gemm_kernel<<<gFfn1, 512, GEMM_SMEM_BYTES>>>(px,
            Wff1 + (size_t)i * Dd * DFFf, Wff1, Wff1, pffn, pffn, pffn, DFFf, Dd, 1);
        mma_gemm_kernel<<<gProj, 512, GEMM_SMEM_BYTES>>>(pffn,
            Wff2 + (size_t)i * DFFf * Dd, Wff2, Wff2, pproj, pproj, pproj, Dd, DFFf, 0);
        ln_kernel<<<Mm, 256>>>(pproj, px, gff + (size_t)i * Dd, bff + (size_t)i * Dd, px);
    }

    copy_kernel<<<(Mm * Dd / 4) / 256, 256>>>(px, x_out);
}